// round 7
// baseline (speedup 1.0000x reference)
#include <cuda_runtime.h>

// SplineNetwork, warp-per-query, butterfly-rank formulation.
// B=16384 queries, 128x128 regular grid, K=9 NN + Keys cubic conv.
//   d_in[0] = x (16384,2) f32 | d_in[1] = weights (16384,1) f32
//   d_in[2] = control_points (16384,2) f32, cp[i*128+j] = (t_i, t_j)
// Output: (out (16384,1), x (16384,2)) -> 49152 floats.
//
// One warp per query; lane i < 25 owns candidate (i/5, i%5) of the
// ROUND-centered 5x5 window {nix-2..nix+2} clamped (R1/R4/R5-certified).
// D bit-matches the reference GEMM expansion:
//   D = rn(rn(x2s + c2) - 2*fma(x1,cy,rn(x0*cx)))
// Rank via xor-butterfly k=1..31: every unordered lane pair hit once;
// tie-break (j < lane) == (lane & highbit(k)) != 0, a hoisted boolean --
// equals ascending-global-index order == jax.lax.top_k stability.
// Lanes 25..31 carry +inf sentinels (always rank last, masked from sum).

#define NGRID 128
#define NC    25
#define KNN   9

__global__ __launch_bounds__(256) void spline_warp_kernel(
    const float* __restrict__ x,
    const float* __restrict__ wts,
    const float* __restrict__ cp,
    float* __restrict__ out,
    int batch)
{
    const unsigned FULL = 0xffffffffu;
    int lane = threadIdx.x & 31;
    int q = blockIdx.x * (blockDim.x >> 5) + (threadIdx.x >> 5);
    if (q >= batch) return;

    // query point (uniform across warp -> broadcast load)
    float2 xv = __ldg((const float2*)x + q);
    float x0 = xv.x, x1 = xv.y;

    // bandwidth h = ||x[0]-x[1]|| (global constant; smooth epilogue term)
    float4 h4 = __ldg((const float4*)x);
    float hdx = h4.x - h4.z;
    float hdy = h4.y - h4.w;
    float inv_h = rsqrtf(fmaf(hdx, hdx, hdy * hdy));

    // round-centered window start, clamped (certified)
    int nix = __float2int_rn((x0 + 1.0f) * 63.5f);
    int niy = __float2int_rn((x1 + 1.0f) * 63.5f);
    int sx = min(max(nix - 2, 0), NGRID - 5);
    int sy = min(max(niy - 2, 0), NGRID - 5);

    // this lane's candidate; lane/5 via mul-shift (exact for lane < 32)
    int row = (lane * 205) >> 10;
    int col = lane - row * 5;
    bool valid = lane < NC;
    int ix = valid ? sx + row : sx;
    int iy = valid ? sy + col : sy;

    // node coords / weight (cx = x-coord of row ix; cy = y-coord of col iy)
    float cx = __ldg(&cp[ix << 8]);
    float cy = __ldg(&cp[2 * iy + 1]);
    float wv = __ldg(&wts[(ix << 7) + iy]);

    // exact reference arithmetic for D
    float x2s = __fadd_rn(__fmul_rn(x0, x0), __fmul_rn(x1, x1));
    float c2  = __fadd_rn(__fmul_rn(cx, cx), __fmul_rn(cy, cy));
    float dot = __fmaf_rn(x1, cy, __fmul_rn(x0, cx));
    float D   = __fsub_rn(__fadd_rn(x2s, c2), __fmul_rn(2.0f, dot));
    if (!valid) D = __int_as_float(0x7f800000);   // +inf sentinel

    // hoisted tie-break booleans: tw(k) == ((lane ^ k) < lane)
    bool tb1  = (lane & 1)  != 0;
    bool tb2  = (lane & 2)  != 0;
    bool tb4  = (lane & 4)  != 0;
    bool tb8  = (lane & 8)  != 0;
    bool tb16 = (lane & 16) != 0;

    int rank = 0;
#pragma unroll
    for (int k = 1; k < 32; ++k) {
        float Dj = __shfl_xor_sync(FULL, D, k);
        bool tw = (k >= 16) ? tb16 : (k >= 8) ? tb8 : (k >= 4) ? tb4
                                   : (k >= 2) ? tb2 : tb1;
        rank += (Dj < D || (Dj == D && tw)) ? 1 : 0;
    }

    // Keys cubic conv epilogue (smooth; plain fp32)
    float dxv = x0 - cx;
    float dyv = x1 - cy;
    float a = sqrtf(fmaf(dxv, dxv, dyv * dyv)) * inv_h;
    float p1 = fmaf(fmaf(1.5f, a, -2.5f), a * a, 1.0f);
    float p2 = fmaf(fmaf(fmaf(-0.5f, a, 2.5f), a, -4.0f), a, 2.0f);
    float cv = (a < 1.0f) ? p1 : ((a < 2.0f) ? p2 : 0.0f);

    float val = (valid && rank < KNN) ? (wv * cv) : 0.0f;

    // warp sum
#pragma unroll
    for (int s = 16; s; s >>= 1)
        val += __shfl_xor_sync(FULL, val, s);

    if (lane == 0) {
        out[q] = val;
        ((float2*)(out + batch))[q] = xv;     // x passthrough
    }
}

extern "C" void kernel_launch(void* const* d_in, const int* in_sizes, int n_in,
                              void* d_out, int out_size)
{
    const float* x  = (const float*)d_in[0];
    const float* w  = (const float*)d_in[1];
    const float* cp = (const float*)d_in[2];
    float* out = (float*)d_out;
    int batch = in_sizes[0] / 2;              // 16384
    int block = 256;                          // 8 warps = 8 queries per CTA
    int warps_per_block = block / 32;
    int grid = (batch + warps_per_block - 1) / warps_per_block;   // 2048
    spline_warp_kernel<<<grid, block>>>(x, w, cp, out, batch);
    (void)n_in; (void)out_size;
}

// round 8
// speedup vs baseline: 1.4250x; 1.4250x over previous
#include <cuda_runtime.h>

// SplineNetwork, warp-per-query + bitonic 9th-order-statistic selection.
// B=16384 queries, 128x128 regular grid, K=9 NN + Keys cubic conv.
//   d_in[0] = x (16384,2) f32 | d_in[1] = weights (16384,1) f32
//   d_in[2] = control_points (16384,2) f32, cp[i*128+j] = (t_i, t_j)
// Output: (out (16384,1), x (16384,2)) -> 49152 floats.
//
// Lane i < 25 owns candidate (i/5, i%5) of the ROUND-centered 5x5 window
// {nix-2..nix+2} clamped to [0,123] (R1/R5/R6-certified window).
// D bit-matches the reference GEMM expansion:
//   D = rn(rn(x2s + c2) - 2*fma(x1,cy,rn(x0*cx)))
// Selection: bitonic-sort a copy of D (15 steps), T9 = 9th smallest;
// select strict D<T9 plus lowest-lane-index ties to fill 9 -- identical to
// jax.lax.top_k's stable ordering. Lanes 25..31 hold +inf (never selected).

#define NGRID 128
#define NC    25
#define KNN   9

__global__ __launch_bounds__(256) void spline_warp_kernel(
    const float* __restrict__ x,
    const float* __restrict__ wts,
    const float* __restrict__ cp,
    float* __restrict__ out,
    int batch)
{
    const unsigned FULL = 0xffffffffu;
    int lane = threadIdx.x & 31;
    int q = blockIdx.x * (blockDim.x >> 5) + (threadIdx.x >> 5);   // grid covers batch exactly

    // query point (uniform across warp)
    float2 xv = __ldg((const float2*)x + q);
    float x0 = xv.x, x1 = xv.y;

    // bandwidth h = ||x[0]-x[1]|| (smooth epilogue term)
    float4 h4 = __ldg((const float4*)x);
    float hdx = h4.x - h4.z;
    float hdy = h4.y - h4.w;
    float inv_h = rsqrtf(fmaf(hdx, hdx, hdy * hdy));

    // round-centered window start, clamped (certified)
    int nix = __float2int_rn((x0 + 1.0f) * 63.5f);
    int niy = __float2int_rn((x1 + 1.0f) * 63.5f);
    int sx = min(max(nix - 2, 0), NGRID - 5);
    int sy = min(max(niy - 2, 0), NGRID - 5);

    // lane's candidate; lane/5 via mul-shift
    int row = (lane * 205) >> 10;
    int col = lane - row * 5;
    bool sentinel = lane >= NC;
    int ix = sx + (sentinel ? 0 : row);
    int iy = sy + (sentinel ? 0 : col);

    // node coords / weight
    float cx = __ldg(&cp[ix << 8]);          // x-coord of grid row ix
    float cy = __ldg(&cp[2 * iy + 1]);       // y-coord of grid col iy
    float wv = __ldg(&wts[(ix << 7) + iy]);

    // exact reference arithmetic for D
    float x2s = __fadd_rn(__fmul_rn(x0, x0), __fmul_rn(x1, x1));
    float c2  = __fadd_rn(__fmul_rn(cx, cx), __fmul_rn(cy, cy));
    float dot = __fmaf_rn(x1, cy, __fmul_rn(x0, cx));
    float D   = __fsub_rn(__fadd_rn(x2s, c2), __fmul_rn(2.0f, dot));
    if (sentinel) D = __int_as_float(0x7f800000);   // +inf

    // ---- bitonic sort (keys only) across 32 lanes: 15 compare-exchange steps
    float S = D;
#pragma unroll
    for (int k = 2; k <= 32; k <<= 1) {
#pragma unroll
        for (int j = k >> 1; j > 0; j >>= 1) {
            float Sp = __shfl_xor_sync(FULL, S, j);
            bool lower = (lane & j) == 0;
            bool asc   = (lane & k) == 0;     // k==32: always ascending
            bool keepmin = (lower == asc);
            float mn = fminf(S, Sp), mx = fmaxf(S, Sp);
            S = keepmin ? mn : mx;
        }
    }
    float T9 = __shfl_sync(FULL, S, KNN - 1);   // 9th smallest

    // ---- stable selection (== top_k: all strict, then ties by lowest index)
    unsigned strictm = __ballot_sync(FULL, D < T9);
    unsigned tiem    = __ballot_sync(FULL, D == T9);
    int m = __popc(strictm);                        // # strictly better (<= 8)
    int tiepos = __popc(tiem & ((1u << lane) - 1)); // my order among ties
    bool sel = (D < T9) || ((D == T9) && (tiepos < KNN - m));

    // ---- Keys cubic conv epilogue (smooth; plain fp32)
    float dxv = x0 - cx;
    float dyv = x1 - cy;
    float a = sqrtf(fmaf(dxv, dxv, dyv * dyv)) * inv_h;
    float p1 = fmaf(fmaf(1.5f, a, -2.5f), a * a, 1.0f);
    float p2 = fmaf(fmaf(fmaf(-0.5f, a, 2.5f), a, -4.0f), a, 2.0f);
    float cv = (a < 1.0f) ? p1 : ((a < 2.0f) ? p2 : 0.0f);

    float val = sel ? (wv * cv) : 0.0f;

    // warp sum
#pragma unroll
    for (int s = 16; s; s >>= 1)
        val += __shfl_xor_sync(FULL, val, s);

    if (lane == 0) {
        out[q] = val;
        ((float2*)(out + batch))[q] = xv;     // x passthrough
    }
}

extern "C" void kernel_launch(void* const* d_in, const int* in_sizes, int n_in,
                              void* d_out, int out_size)
{
    const float* x  = (const float*)d_in[0];
    const float* w  = (const float*)d_in[1];
    const float* cp = (const float*)d_in[2];
    float* out = (float*)d_out;
    int batch = in_sizes[0] / 2;              // 16384
    int block = 256;                          // 8 warps = 8 queries per CTA
    int warps_per_block = block / 32;
    int grid = (batch + warps_per_block - 1) / warps_per_block;   // 2048, exact
    spline_warp_kernel<<<grid, block>>>(x, w, cp, out, batch);
    (void)n_in; (void)out_size;
}

// round 9
// speedup vs baseline: 1.4723x; 1.0332x over previous
#include <cuda_runtime.h>

// SplineNetwork, 2-queries-per-warp bitonic 9th-order-statistic selection.
// B=16384 queries, 128x128 regular grid, K=9 NN + Keys cubic conv.
//   d_in[0] = x (16384,2) f32 | d_in[1] = weights (16384,1) f32
//   d_in[2] = control_points (16384,2) f32, cp[i*128+j] = (t_i, t_j)
// Output: (out (16384,1), x (16384,2)) -> 49152 floats.
//
// Per query (unchanged, certified R5/R8): lane i < 25 owns candidate
// (i/5, i%5) of the ROUND-centered 5x5 window {nix-2..nix+2} clamped to
// [0,123]. D bit-matches the reference GEMM expansion:
//   D = rn(rn(x2s + c2) - 2*fma(x1,cy,rn(x0*cx)))
// T9 = 9th smallest via 15-step bitonic (lanes 25..31 = +inf), stable
// selection via ballots (strict < plus lowest-index ties) == lax.top_k.
// Two independent queries interleaved per warp: halves warp count to 8192
// (single wave on 148 SMs) and doubles intra-warp ILP on the SHFL chains.

#define NGRID 128
#define NC    25
#define KNN   9

__global__ __launch_bounds__(256) void spline_warp2_kernel(
    const float* __restrict__ x,
    const float* __restrict__ wts,
    const float* __restrict__ cp,
    float* __restrict__ out,
    int batch)
{
    const unsigned FULL = 0xffffffffu;
    int lane = threadIdx.x & 31;
    int w = blockIdx.x * (blockDim.x >> 5) + (threadIdx.x >> 5);
    int q0 = 2 * w;
    int q1 = q0 + 1;                       // batch even; grid exact

    float2 xv0 = __ldg((const float2*)x + q0);
    float2 xv1 = __ldg((const float2*)x + q1);

    // bandwidth h = ||x[0]-x[1]|| (smooth epilogue term, warp-uniform)
    float4 h4 = __ldg((const float4*)x);
    float hdx = h4.x - h4.z;
    float hdy = h4.y - h4.w;
    float inv_h = rsqrtf(fmaf(hdx, hdx, hdy * hdy));

    // lane's local candidate offsets
    int row = (lane * 205) >> 10;          // lane / 5
    int col = lane - row * 5;
    bool sentinel = lane >= NC;
    if (sentinel) { row = 0; col = 0; }

    // ---- per-query window + candidate data
    int nix0 = __float2int_rn((xv0.x + 1.0f) * 63.5f);
    int niy0 = __float2int_rn((xv0.y + 1.0f) * 63.5f);
    int sx0 = min(max(nix0 - 2, 0), NGRID - 5);
    int sy0 = min(max(niy0 - 2, 0), NGRID - 5);
    int nix1 = __float2int_rn((xv1.x + 1.0f) * 63.5f);
    int niy1 = __float2int_rn((xv1.y + 1.0f) * 63.5f);
    int sx1 = min(max(nix1 - 2, 0), NGRID - 5);
    int sy1 = min(max(niy1 - 2, 0), NGRID - 5);

    int ix0 = sx0 + row, iy0 = sy0 + col;
    int ix1 = sx1 + row, iy1 = sy1 + col;

    float cx0 = __ldg(&cp[ix0 << 8]);
    float cy0 = __ldg(&cp[2 * iy0 + 1]);
    float wv0 = __ldg(&wts[(ix0 << 7) + iy0]);
    float cx1 = __ldg(&cp[ix1 << 8]);
    float cy1 = __ldg(&cp[2 * iy1 + 1]);
    float wv1 = __ldg(&wts[(ix1 << 7) + iy1]);

    // ---- exact reference arithmetic for D (certified chain)
    float x2s0 = __fadd_rn(__fmul_rn(xv0.x, xv0.x), __fmul_rn(xv0.y, xv0.y));
    float c20  = __fadd_rn(__fmul_rn(cx0, cx0), __fmul_rn(cy0, cy0));
    float dot0 = __fmaf_rn(xv0.y, cy0, __fmul_rn(xv0.x, cx0));
    float D0   = __fsub_rn(__fadd_rn(x2s0, c20), __fmul_rn(2.0f, dot0));
    float x2s1 = __fadd_rn(__fmul_rn(xv1.x, xv1.x), __fmul_rn(xv1.y, xv1.y));
    float c21  = __fadd_rn(__fmul_rn(cx1, cx1), __fmul_rn(cy1, cy1));
    float dot1 = __fmaf_rn(xv1.y, cy1, __fmul_rn(xv1.x, cx1));
    float D1   = __fsub_rn(__fadd_rn(x2s1, c21), __fmul_rn(2.0f, dot1));
    const float INF = __int_as_float(0x7f800000);
    if (sentinel) { D0 = INF; D1 = INF; }

    // ---- interleaved bitonic sorts (15 steps each, independent -> ILP)
    float S0 = D0, S1 = D1;
#pragma unroll
    for (int k = 2; k <= 32; k <<= 1) {
#pragma unroll
        for (int j = k >> 1; j > 0; j >>= 1) {
            float Sp0 = __shfl_xor_sync(FULL, S0, j);
            float Sp1 = __shfl_xor_sync(FULL, S1, j);
            bool keepmin = ((lane & j) == 0) == ((lane & k) == 0);
            S0 = keepmin ? fminf(S0, Sp0) : fmaxf(S0, Sp0);
            S1 = keepmin ? fminf(S1, Sp1) : fmaxf(S1, Sp1);
        }
    }
    float T9_0 = __shfl_sync(FULL, S0, KNN - 1);
    float T9_1 = __shfl_sync(FULL, S1, KNN - 1);

    // ---- stable selection (== top_k): strict <, ties by lowest lane index
    unsigned below = (1u << lane) - 1u;
    unsigned strict0 = __ballot_sync(FULL, D0 < T9_0);
    unsigned tie0    = __ballot_sync(FULL, D0 == T9_0);
    bool sel0 = (D0 < T9_0) ||
                ((D0 == T9_0) && (__popc(tie0 & below) < KNN - __popc(strict0)));
    unsigned strict1 = __ballot_sync(FULL, D1 < T9_1);
    unsigned tie1    = __ballot_sync(FULL, D1 == T9_1);
    bool sel1 = (D1 < T9_1) ||
                ((D1 == T9_1) && (__popc(tie1 & below) < KNN - __popc(strict1)));

    // ---- Keys cubic conv epilogue (smooth; plain fp32)
    float dx0 = xv0.x - cx0, dy0 = xv0.y - cy0;
    float a0 = sqrtf(fmaf(dx0, dx0, dy0 * dy0)) * inv_h;
    float p10 = fmaf(fmaf(1.5f, a0, -2.5f), a0 * a0, 1.0f);
    float p20 = fmaf(fmaf(fmaf(-0.5f, a0, 2.5f), a0, -4.0f), a0, 2.0f);
    float cv0 = (a0 < 1.0f) ? p10 : ((a0 < 2.0f) ? p20 : 0.0f);
    float dx1 = xv1.x - cx1, dy1 = xv1.y - cy1;
    float a1 = sqrtf(fmaf(dx1, dx1, dy1 * dy1)) * inv_h;
    float p11 = fmaf(fmaf(1.5f, a1, -2.5f), a1 * a1, 1.0f);
    float p21 = fmaf(fmaf(fmaf(-0.5f, a1, 2.5f), a1, -4.0f), a1, 2.0f);
    float cv1 = (a1 < 1.0f) ? p11 : ((a1 < 2.0f) ? p21 : 0.0f);

    float v0 = sel0 ? (wv0 * cv0) : 0.0f;
    float v1 = sel1 ? (wv1 * cv1) : 0.0f;

    // ---- interleaved warp sums (result lands in all lanes)
#pragma unroll
    for (int s = 16; s; s >>= 1) {
        v0 += __shfl_xor_sync(FULL, v0, s);
        v1 += __shfl_xor_sync(FULL, v1, s);
    }

    if (lane == 0) {
        out[q0] = v0;
        ((float2*)(out + batch))[q0] = xv0;
    } else if (lane == 1) {
        out[q1] = v1;
        ((float2*)(out + batch))[q1] = xv1;
    }
}

extern "C" void kernel_launch(void* const* d_in, const int* in_sizes, int n_in,
                              void* d_out, int out_size)
{
    const float* x  = (const float*)d_in[0];
    const float* w  = (const float*)d_in[1];
    const float* cp = (const float*)d_in[2];
    float* out = (float*)d_out;
    int batch = in_sizes[0] / 2;              // 16384
    int block = 256;                          // 8 warps = 16 queries per CTA
    int queries_per_block = (block / 32) * 2;
    int grid = (batch + queries_per_block - 1) / queries_per_block;   // 1024
    spline_warp2_kernel<<<grid, block>>>(x, w, cp, out, batch);
    (void)n_in; (void)out_size;
}

// round 10
// speedup vs baseline: 1.5465x; 1.0504x over previous
#include <cuda_runtime.h>

// SplineNetwork, half-warp-per-query (16 lanes/query, 2 queries/warp).
// B=16384 queries, 128x128 regular grid, K=9 NN + Keys cubic conv.
//   d_in[0] = x (16384,2) f32 | d_in[1] = weights (16384,1) f32
//   d_in[2] = control_points (16384,2) f32, cp[i*128+j] = (t_i, t_j)
// Output: (out (16384,1), x (16384,2)) -> 49152 floats.
//
// Interior fast path (i0x,i0y in [1,125]): floor-4x4 window {i0-1..i0+2},
// 16 candidates on 16 lanes. Proven: in-window 9th-NN <= 3.25h^2, excluded
// nodes >= 4h^2 (margin 0.75h^2 >> fp noise). Edge queries (~3-6%) take the
// R8-certified full-warp 5x5 round-centered 25-candidate path (warp-uniform
// branch). D bit-matches reference: rn(rn(x2s+c2) - 2*fma(x1,cy,rn(x0*cx)));
// stable tie selection (lowest global index) == jax.lax.top_k.

#define NGRID 128
#define KNN   9

// Full-warp 25-candidate fallback (R8 logic). Returns the query's output
// value broadcast to all lanes.
__device__ __forceinline__ float process_q25(
    float2 xv, const float* __restrict__ cp, const float* __restrict__ wts,
    float inv_h, int lane)
{
    const unsigned FULL = 0xffffffffu;
    int nix = __float2int_rn((xv.x + 1.0f) * 63.5f);
    int niy = __float2int_rn((xv.y + 1.0f) * 63.5f);
    int sx = min(max(nix - 2, 0), NGRID - 5);
    int sy = min(max(niy - 2, 0), NGRID - 5);

    int row = (lane * 205) >> 10;      // lane / 5
    int col = lane - row * 5;
    bool sentinel = lane >= 25;
    int ix = sx + (sentinel ? 0 : row);
    int iy = sy + (sentinel ? 0 : col);

    float cx = __ldg(&cp[ix << 8]);
    float cy = __ldg(&cp[2 * iy + 1]);
    float wv = __ldg(&wts[(ix << 7) + iy]);

    float x2s = __fadd_rn(__fmul_rn(xv.x, xv.x), __fmul_rn(xv.y, xv.y));
    float c2  = __fadd_rn(__fmul_rn(cx, cx), __fmul_rn(cy, cy));
    float dot = __fmaf_rn(xv.y, cy, __fmul_rn(xv.x, cx));
    float D   = __fsub_rn(__fadd_rn(x2s, c2), __fmul_rn(2.0f, dot));
    if (sentinel) D = __int_as_float(0x7f800000);

    float S = D;
#pragma unroll
    for (int k = 2; k <= 32; k <<= 1) {
#pragma unroll
        for (int j = k >> 1; j > 0; j >>= 1) {
            float Sp = __shfl_xor_sync(FULL, S, j);
            bool keepmin = ((lane & j) == 0) == ((lane & k) == 0);
            S = keepmin ? fminf(S, Sp) : fmaxf(S, Sp);
        }
    }
    float T9 = __shfl_sync(FULL, S, KNN - 1);

    unsigned below  = (1u << lane) - 1u;
    unsigned strict = __ballot_sync(FULL, D < T9);
    unsigned tie    = __ballot_sync(FULL, D == T9);
    bool sel = (D < T9) ||
               ((D == T9) && (__popc(tie & below) < KNN - __popc(strict)));

    float dxv = xv.x - cx, dyv = xv.y - cy;
    float a = sqrtf(fmaf(dxv, dxv, dyv * dyv)) * inv_h;
    float p1 = fmaf(fmaf(1.5f, a, -2.5f), a * a, 1.0f);
    float p2 = fmaf(fmaf(fmaf(-0.5f, a, 2.5f), a, -4.0f), a, 2.0f);
    float cv = (a < 1.0f) ? p1 : ((a < 2.0f) ? p2 : 0.0f);

    float val = sel ? (wv * cv) : 0.0f;
#pragma unroll
    for (int s = 16; s; s >>= 1)
        val += __shfl_xor_sync(FULL, val, s);
    return val;
}

__global__ __launch_bounds__(256) void spline_hw_kernel(
    const float* __restrict__ x,
    const float* __restrict__ wts,
    const float* __restrict__ cp,
    float* __restrict__ out,
    int batch)
{
    const unsigned FULL = 0xffffffffu;
    int lane = threadIdx.x & 31;
    int h = lane & 15;                 // lane within half-warp
    int half = lane >> 4;              // 0 or 1
    int w = blockIdx.x * (blockDim.x >> 5) + (threadIdx.x >> 5);
    int q0 = 2 * w;

    float2 xv0 = __ldg((const float2*)x + q0);
    float2 xv1 = __ldg((const float2*)x + q0 + 1);
    float2 xq  = half ? xv1 : xv0;     // this half's query

    // bandwidth h = ||x[0]-x[1]|| (smooth epilogue term, warp-uniform)
    float4 h4 = __ldg((const float4*)x);
    float hdx = h4.x - h4.z;
    float hdy = h4.y - h4.w;
    float inv_h = rsqrtf(fmaf(hdx, hdx, hdy * hdy));

    // floor cell index for this half's query
    int i0x = (int)floorf((xq.x + 1.0f) * 63.5f);
    int i0y = (int)floorf((xq.y + 1.0f) * 63.5f);

    // warp-uniform edge predicate over both queries
    bool edge_me = (i0x < 1) | (i0x > 125) | (i0y < 1) | (i0y > 125);
    unsigned eb = __ballot_sync(FULL, edge_me);

    float v0, v1;
    if (eb == 0u) {
        // ---- fast path: floor-4x4, 16 candidates on this half's 16 lanes
        int ix = i0x - 1 + (h >> 2);
        int iy = i0y - 1 + (h & 3);

        float cx = __ldg(&cp[ix << 8]);         // x-coord of grid row ix
        float cy = __ldg(&cp[2 * iy + 1]);      // y-coord of grid col iy
        float wv = __ldg(&wts[(ix << 7) + iy]);

        // exact reference arithmetic for D (certified chain)
        float x2s = __fadd_rn(__fmul_rn(xq.x, xq.x), __fmul_rn(xq.y, xq.y));
        float c2  = __fadd_rn(__fmul_rn(cx, cx), __fmul_rn(cy, cy));
        float dot = __fmaf_rn(xq.y, cy, __fmul_rn(xq.x, cx));
        float D   = __fsub_rn(__fadd_rn(x2s, c2), __fmul_rn(2.0f, dot));

        // bitonic-16 within each half (strides <= 8 stay in-half); each
        // shfl advances BOTH queries simultaneously.
        float S = D;
#pragma unroll
        for (int k = 2; k <= 16; k <<= 1) {
#pragma unroll
            for (int j = k >> 1; j > 0; j >>= 1) {
                float Sp = __shfl_xor_sync(FULL, S, j);
                bool keepmin = ((h & j) == 0) == ((h & k) == 0);  // k=16: asc
                S = keepmin ? fminf(S, Sp) : fmaxf(S, Sp);
            }
        }
        // 9th smallest of own half: sorted position 8
        float T9 = __shfl_sync(FULL, S, (lane & 16) | 8);

        // stable selection within half (enumeration order h == ascending
        // global candidate index)
        unsigned strict = __ballot_sync(FULL, D < T9);
        unsigned tie    = __ballot_sync(FULL, D == T9);
        unsigned hs = half ? (strict >> 16) : (strict & 0xFFFFu);
        unsigned ht = half ? (tie >> 16)    : (tie & 0xFFFFu);
        unsigned belh = (1u << h) - 1u;
        bool sel = (D < T9) ||
                   ((D == T9) && (__popc(ht & belh) < KNN - __popc(hs)));

        // Keys cubic conv epilogue
        float dxv = xq.x - cx, dyv = xq.y - cy;
        float a = sqrtf(fmaf(dxv, dxv, dyv * dyv)) * inv_h;
        float p1 = fmaf(fmaf(1.5f, a, -2.5f), a * a, 1.0f);
        float p2 = fmaf(fmaf(fmaf(-0.5f, a, 2.5f), a, -4.0f), a, 2.0f);
        float cv = (a < 1.0f) ? p1 : ((a < 2.0f) ? p2 : 0.0f);

        float val = sel ? (wv * cv) : 0.0f;
        // 4-step half-warp sum (both halves in parallel)
#pragma unroll
        for (int s = 8; s; s >>= 1)
            val += __shfl_xor_sync(FULL, val, s);

        v0 = __shfl_sync(FULL, val, 0);
        v1 = __shfl_sync(FULL, val, 16);
    } else {
        // ---- edge fallback: R8-certified full-warp 25-candidate path, twice
        v0 = process_q25(xv0, cp, wts, inv_h, lane);
        v1 = process_q25(xv1, cp, wts, inv_h, lane);
    }

    if (lane == 0) {
        out[q0]     = v0;
        out[q0 + 1] = v1;
        ((float2*)(out + batch))[q0]     = xv0;
        ((float2*)(out + batch))[q0 + 1] = xv1;
    }
}

extern "C" void kernel_launch(void* const* d_in, const int* in_sizes, int n_in,
                              void* d_out, int out_size)
{
    const float* x  = (const float*)d_in[0];
    const float* w  = (const float*)d_in[1];
    const float* cp = (const float*)d_in[2];
    float* out = (float*)d_out;
    int batch = in_sizes[0] / 2;              // 16384
    int block = 256;                          // 8 warps = 16 queries per CTA
    int queries_per_block = (block / 32) * 2;
    int grid = (batch + queries_per_block - 1) / queries_per_block;   // 1024
    spline_hw_kernel<<<grid, block>>>(x, w, cp, out, batch);
    (void)n_in; (void)out_size;
}